// round 1
// baseline (speedup 1.0000x reference)
#include <cuda_runtime.h>
#include <cstdint>

#define FLOOR_V 1e-6f
#define MELS 128
#define FRAMES 1024

// One warp per (batch, time) row of 128 mel bins.
// Closed-form separable replacement for the width-axis conv:
//   smoothed[w] = alpha^(511-w) * R / S,  R = sum_m x[m] * alpha^m
// Fast path (always taken for this data): smoothed clamps to FLOOR everywhere,
// so smoothed^-alpha is the warp-uniform constant KA = FLOOR^-alpha.
__global__ __launch_bounds__(256, 8)
void pcen_kernel(const float* __restrict__ in,
                 const float* __restrict__ p_alpha,
                 const float* __restrict__ p_delta,
                 const float* __restrict__ p_root,
                 float* __restrict__ out,
                 int num_rows) {
    const float alpha = __ldg(p_alpha);
    const float delta = __ldg(p_delta);
    const float root  = __ldg(p_root);

    const int lane = threadIdx.x & 31;
    const int warp_global = (blockIdx.x * blockDim.x + threadIdx.x) >> 5;
    const int nwarps = (gridDim.x * blockDim.x) >> 5;

    // ---- warp/thread-invariant derived constants (amortized over many rows) ----
    const float la = __log2f(alpha);                 // log2(alpha)
    // S = sum_{i=0}^{FRAMES-1} alpha^i (geometric closed form; alpha != 1 here)
    float S;
    {
        const float one_minus_a = 1.0f - alpha;
        if (fabsf(one_minus_a) > 1e-12f)
            S = (1.0f - exp2f((float)FRAMES * la)) / one_minus_a;
        else
            S = (float)FRAMES;
    }
    const float KA    = __powf(FLOOR_V, -alpha);     // FLOOR^-alpha
    const float droot = __powf(delta, root);         // delta^root
    const float inv_S = 1.0f / S;
    const float ralpha = 1.0f / alpha;

    // Per-lane dot weights alpha^m for m = 4*lane + i
    const float w0 = exp2f((float)(4 * lane) * la);
    const float w1 = w0 * alpha;
    const float w2 = w1 * alpha;
    const float w3 = w2 * alpha;

    // Per-lane conv coefficients c_w = alpha^(511 - w) / S, w = 4*lane + i
    const float c0 = exp2f((float)((FRAMES / 2 - 1) - 4 * lane) * la) * inv_S;
    const float c1 = c0 * ralpha;
    const float c2 = c1 * ralpha;
    const float c3 = c2 * ralpha;

    // Upper bound coefficient over all w in [0, 127] (handles alpha<1 and alpha>1)
    const float cb = fmaxf(exp2f((float)(FRAMES / 2 - 1) * la),
                           exp2f((float)(FRAMES / 2 - MELS) * la)) * inv_S;

    const float4* __restrict__ in4  = reinterpret_cast<const float4*>(in);
    float4* __restrict__       out4 = reinterpret_cast<float4*>(out);

    for (int row = warp_global; row < num_rows; row += nwarps) {
        const int idx = row * (MELS / 4) + lane;
        const float4 v = in4[idx];

        const float x0 = fmaxf(v.x, FLOOR_V);
        const float x1 = fmaxf(v.y, FLOOR_V);
        const float x2 = fmaxf(v.z, FLOOR_V);
        const float x3 = fmaxf(v.w, FLOOR_V);

        // Row dot R = sum_m x[m] * alpha^m
        float part = x0 * w0;
        part = fmaf(x1, w1, part);
        part = fmaf(x2, w2, part);
        part = fmaf(x3, w3, part);
        part += __shfl_xor_sync(0xffffffffu, part, 16);
        part += __shfl_xor_sync(0xffffffffu, part, 8);
        part += __shfl_xor_sync(0xffffffffu, part, 4);
        part += __shfl_xor_sync(0xffffffffu, part, 2);
        part += __shfl_xor_sync(0xffffffffu, part, 1);
        const float R = part;  // broadcast to all lanes

        float pm0, pm1, pm2, pm3;
        if (R * cb <= FLOOR_V) {
            // All smoothed values clamp to FLOOR -> uniform constant (hot path)
            pm0 = KA; pm1 = KA; pm2 = KA; pm3 = KA;
        } else {
            // General path (not taken for this data, kept for correctness)
            pm0 = __powf(fmaxf(c0 * R, FLOOR_V), -alpha);
            pm1 = __powf(fmaxf(c1 * R, FLOOR_V), -alpha);
            pm2 = __powf(fmaxf(c2 * R, FLOOR_V), -alpha);
            pm3 = __powf(fmaxf(c3 * R, FLOOR_V), -alpha);
        }

        float4 o;
        o.x = __powf(fmaf(x0, pm0, delta), root) - droot;
        o.y = __powf(fmaf(x1, pm1, delta), root) - droot;
        o.z = __powf(fmaf(x2, pm2, delta), root) - droot;
        o.w = __powf(fmaf(x3, pm3, delta), root) - droot;

        out4[idx] = o;
    }
}

extern "C" void kernel_launch(void* const* d_in, const int* in_sizes, int n_in,
                              void* d_out, int out_size) {
    const float* inputs = (const float*)d_in[0];
    const float* alpha  = (const float*)d_in[1];
    const float* delta  = (const float*)d_in[2];
    const float* root   = (const float*)d_in[3];
    float* out = (float*)d_out;

    const int num_rows = in_sizes[0] / MELS;  // 64 * 1024 = 65536

    const int threads = 256;
    const int blocks = 1184;  // 148 SMs * 8 blocks, grid-stride over rows
    pcen_kernel<<<blocks, threads>>>(inputs, alpha, delta, root, out, num_rows);
}